// round 7
// baseline (speedup 1.0000x reference)
#include <cuda_runtime.h>

#define BATCH   4
#define NPTS    4096
#define TS      128
#define MICRO   8
#define TDIM    16
#define THREADS (TDIM * TDIM)        // 256
#define NBLK    (NPTS / TS)          // 32 tiles per dim
#define CTPB    8                    // col tiles per block
#define CGRPS   (NBLK / CTPB)        // 4
#define GRID_T  (CGRPS * NBLK * BATCH)   // 512 blocks
#define HALFK   (BATCH * NPTS)       // 16384
#define NKEY    (2 * HALFK)          // 32768 keys = 128 KB

// Bit-inverted distance keys: key = ~bits(d), d>=0 => max(key) == min(d) and
// every valid key > 0, so ZERO is the identity. The last-ticket block restores
// zeros after consuming, so every graph replay starts clean. No init kernel.
__device__ unsigned g_key[NKEY];
__device__ unsigned g_cnt;           // zero-init; reset by last block

__device__ __forceinline__ float fsub1(float a, float b) {   // a - b, FFMA-imm
    float r;
    asm("fma.rn.f32 %0, %1, 0fBF800000, %2;" : "=f"(r) : "f"(b), "f"(a));
    return r;
}

__global__ __launch_bounds__(THREADS)
void chamfer_onekernel(const float* __restrict__ pred,
                       const float* __restrict__ gt,
                       float* __restrict__ out) {
    const int tx   = threadIdx.x & (TDIM - 1);
    const int ty   = threadIdx.x >> 4;
    const int cgrp = blockIdx.x;          // 0..3  (8 col tiles each)
    const int rblk = blockIdx.y;          // 0..31
    const int b    = blockIdx.z;

    __shared__ float    swcol[8][TS];
    __shared__ unsigned s_ticket;
    __shared__ float    s_sum[8];

    const float* prow = pred + (size_t)b * NPTS * 3;
    const float* pcol = gt   + (size_t)b * NPTS * 3;
    const int r0 = rblk * TS + ty * MICRO;

    // Row coords: 8 points = 24 floats = 6 aligned LDG.128 (persist all tiles)
    float4 rb4[6];
    {
        const float4* rp = reinterpret_cast<const float4*>(prow + r0 * 3);
        #pragma unroll
        for (int i = 0; i < 6; i++) rb4[i] = rp[i];
    }
    const float* rr = reinterpret_cast<const float*>(rb4);
    float rx[MICRO], ry[MICRO], rz[MICRO], rmin[MICRO];
    #pragma unroll
    for (int i = 0; i < MICRO; i++) {
        rx[i] = rr[3 * i]; ry[i] = rr[3 * i + 1]; rz[i] = rr[3 * i + 2];
        rmin[i] = 3.4e38f;
    }

    const int warp = threadIdx.x >> 5;
    const int lane = threadIdx.x & 31;

    #pragma unroll 1
    for (int t = 0; t < CTPB; t++) {
        const int cbase = (cgrp * CTPB + t) * TS;
        const int c0 = cbase + tx * MICRO;

        float4 cb4[6];
        {
            const float4* cp = reinterpret_cast<const float4*>(pcol + c0 * 3);
            #pragma unroll
            for (int i = 0; i < 6; i++) cb4[i] = cp[i];
        }
        const float* cc = reinterpret_cast<const float*>(cb4);
        float cx[MICRO], cy[MICRO], cz[MICRO], cmin[MICRO];
        #pragma unroll
        for (int j = 0; j < MICRO; j++) {
            cx[j] = cc[3 * j]; cy[j] = cc[3 * j + 1]; cz[j] = cc[3 * j + 2];
            cmin[j] = 3.4e38f;
        }

        // 64 pairs: 3 FFMA-imm + 2 FADD (|.| folded) + 2 FMNMX
        #pragma unroll
        for (int i = 0; i < MICRO; i++) {
            #pragma unroll
            for (int j = 0; j < MICRO; j++) {
                const float dx = fsub1(rx[i], cx[j]);
                const float dy = fsub1(ry[i], cy[j]);
                const float dz = fsub1(rz[i], cz[j]);
                const float d  = (fabsf(dx) + fabsf(dy)) + fabsf(dz);
                rmin[i] = fminf(rmin[i], d);
                cmin[j] = fminf(cmin[j], d);
            }
        }

        // Col epilogue: xor16 fold, lanes<16 STS, min across 8 warps, REDG.MAX
        #pragma unroll
        for (int j = 0; j < MICRO; j++)
            cmin[j] = fminf(cmin[j], __shfl_xor_sync(0xffffffffu, cmin[j], 16));
        if (lane < 16) {
            #pragma unroll
            for (int j = 0; j < MICRO; j++)
                swcol[warp][lane * MICRO + j] = cmin[j];
        }
        __syncthreads();
        if (threadIdx.x < TS) {
            float m = swcol[0][threadIdx.x];
            #pragma unroll
            for (int w = 1; w < 8; w++)
                m = fminf(m, swcol[w][threadIdx.x]);
            atomicMax(&g_key[HALFK + b * NPTS + cbase + threadIdx.x],
                      ~__float_as_uint(m));
        }
        __syncthreads();   // swcol reused next tile
    }

    // Row epilogue (once): fold across the 16 tx lanes, tx==0 publishes.
    #pragma unroll
    for (int i = 0; i < MICRO; i++) {
        #pragma unroll
        for (int o = 1; o < TDIM; o <<= 1)
            rmin[i] = fminf(rmin[i], __shfl_xor_sync(0xffffffffu, rmin[i], o));
    }
    if (tx == 0) {
        #pragma unroll
        for (int i = 0; i < MICRO; i++)
            atomicMax(&g_key[b * NPTS + r0 + i], ~__float_as_uint(rmin[i]));
    }

    // --- last-block reduction (no second launch) ---
    __threadfence();                       // order this thread's REDGs
    __syncthreads();
    if (threadIdx.x == 0)
        s_ticket = atomicAdd(&g_cnt, 1u);  // release/acquire point
    __syncthreads();
    if (s_ticket != GRID_T - 1) return;

    // All 512 blocks' fenced REDGs are visible. Read via L2 (__ldcg),
    // restore the zero identity for the next graph replay.
    float sum = 0.0f;
    uint4* base = reinterpret_cast<uint4*>(g_key);
    #pragma unroll 4
    for (int i = threadIdx.x; i < NKEY / 4; i += THREADS) {
        const uint4 k = __ldcg(base + i);
        base[i] = make_uint4(0u, 0u, 0u, 0u);
        sum += __uint_as_float(~k.x) + __uint_as_float(~k.y)
             + __uint_as_float(~k.z) + __uint_as_float(~k.w);
    }
    #pragma unroll
    for (int o = 16; o; o >>= 1)
        sum += __shfl_xor_sync(0xffffffffu, sum, o);
    if (lane == 0) s_sum[warp] = sum;
    __syncthreads();
    if (threadIdx.x == 0) {
        float v = 0.0f;
        #pragma unroll
        for (int w = 0; w < 8; w++) v += s_sum[w];
        out[0] = v * (1.0f / ((float)BATCH * (float)NPTS));
        g_cnt = 0u;                        // reset for next replay
    }
}

extern "C" void kernel_launch(void* const* d_in, const int* in_sizes, int n_in,
                              void* d_out, int out_size) {
    const float* pred = (const float*)d_in[0];
    const float* gt   = (const float*)d_in[1];
    float* out = (float*)d_out;
    (void)in_sizes; (void)n_in; (void)out_size;

    dim3 grid(CGRPS, NBLK, BATCH);    // 4 x 32 x 4 = 512 blocks
    chamfer_onekernel<<<grid, THREADS>>>(pred, gt, out);
}

// round 8
// speedup vs baseline: 1.0691x; 1.0691x over previous
#include <cuda_runtime.h>

#define BATCH   4
#define NPTS    4096
#define TS      128
#define MICRO   8
#define TDIM    16
#define THREADS (TDIM * TDIM)        // 256
#define NBLK    (NPTS / TS)          // 32 tiles per dim
#define CTPB    4                    // col tiles per block
#define CGRPS   (NBLK / CTPB)        // 8
#define GRID_T  (CGRPS * NBLK * BATCH)   // 1024 blocks
#define HALFK   (BATCH * NPTS)       // 16384
#define NKEY    (2 * HALFK)          // 32768 keys = 128 KB

// Bit-inverted distance keys: key = ~bits(d), d>=0 => max(key) == min(d) and
// every valid key > 0, so ZERO is the identity. The last-ticket block restores
// zeros after consuming, so every graph replay starts clean. No init kernel.
__device__ unsigned g_key[NKEY];
__device__ unsigned g_cnt;           // zero-init; reset by last block

__device__ __forceinline__ float fsub1(float a, float b) {   // a - b, FFMA-imm
    float r;
    asm("fma.rn.f32 %0, %1, 0fBF800000, %2;" : "=f"(r) : "f"(b), "f"(a));
    return r;
}

__global__ __launch_bounds__(THREADS, 3)   // reg budget ~84: no spills
void chamfer_onekernel(const float* __restrict__ pred,
                       const float* __restrict__ gt,
                       float* __restrict__ out) {
    const int tx   = threadIdx.x & (TDIM - 1);
    const int ty   = threadIdx.x >> 4;
    const int cgrp = blockIdx.x;          // 0..7  (4 col tiles each)
    const int rblk = blockIdx.y;          // 0..31
    const int b    = blockIdx.z;

    __shared__ float    swcol[2][8][TS];  // double-buffered: 1 sync per tile
    __shared__ unsigned s_ticket;
    __shared__ float    s_sum[8];

    const float* prow = pred + (size_t)b * NPTS * 3;
    const float* pcol = gt   + (size_t)b * NPTS * 3;
    const int r0 = rblk * TS + ty * MICRO;

    // Row coords: 8 points = 24 floats = 6 aligned LDG.128 (persist all tiles)
    float4 rb4[6];
    {
        const float4* rp = reinterpret_cast<const float4*>(prow + r0 * 3);
        #pragma unroll
        for (int i = 0; i < 6; i++) rb4[i] = rp[i];
    }
    const float* rr = reinterpret_cast<const float*>(rb4);
    float rx[MICRO], ry[MICRO], rz[MICRO], rmin[MICRO];
    #pragma unroll
    for (int i = 0; i < MICRO; i++) {
        rx[i] = rr[3 * i]; ry[i] = rr[3 * i + 1]; rz[i] = rr[3 * i + 2];
        rmin[i] = 3.4e38f;
    }

    const int warp = threadIdx.x >> 5;
    const int lane = threadIdx.x & 31;

    #pragma unroll 1
    for (int t = 0; t < CTPB; t++) {
        const int cbase = (cgrp * CTPB + t) * TS;
        const int c0 = cbase + tx * MICRO;
        const int buf = t & 1;

        float4 cb4[6];
        {
            const float4* cp = reinterpret_cast<const float4*>(pcol + c0 * 3);
            #pragma unroll
            for (int i = 0; i < 6; i++) cb4[i] = cp[i];
        }
        const float* cc = reinterpret_cast<const float*>(cb4);
        float cx[MICRO], cy[MICRO], cz[MICRO], cmin[MICRO];
        #pragma unroll
        for (int j = 0; j < MICRO; j++) {
            cx[j] = cc[3 * j]; cy[j] = cc[3 * j + 1]; cz[j] = cc[3 * j + 2];
            cmin[j] = 3.4e38f;
        }

        // 64 pairs: 3 FFMA-imm + 2 FADD (|.| folded) + 2 FMNMX
        #pragma unroll
        for (int i = 0; i < MICRO; i++) {
            #pragma unroll
            for (int j = 0; j < MICRO; j++) {
                const float dx = fsub1(rx[i], cx[j]);
                const float dy = fsub1(ry[i], cy[j]);
                const float dz = fsub1(rz[i], cz[j]);
                const float d  = (fabsf(dx) + fabsf(dy)) + fabsf(dz);
                rmin[i] = fminf(rmin[i], d);
                cmin[j] = fminf(cmin[j], d);
            }
        }

        // Col epilogue: xor16 fold, lanes<16 STS, min across 8 warps, REDG.MAX
        #pragma unroll
        for (int j = 0; j < MICRO; j++)
            cmin[j] = fminf(cmin[j], __shfl_xor_sync(0xffffffffu, cmin[j], 16));
        if (lane < 16) {
            #pragma unroll
            for (int j = 0; j < MICRO; j++)
                swcol[buf][warp][lane * MICRO + j] = cmin[j];
        }
        __syncthreads();
        if (threadIdx.x < TS) {
            float m = swcol[buf][0][threadIdx.x];
            #pragma unroll
            for (int w = 1; w < 8; w++)
                m = fminf(m, swcol[buf][w][threadIdx.x]);
            atomicMax(&g_key[HALFK + b * NPTS + cbase + threadIdx.x],
                      ~__float_as_uint(m));
        }
        // no second sync: next tile writes the other buffer
    }

    // Row epilogue (once): fold across the 16 tx lanes, tx==0 publishes.
    #pragma unroll
    for (int i = 0; i < MICRO; i++) {
        #pragma unroll
        for (int o = 1; o < TDIM; o <<= 1)
            rmin[i] = fminf(rmin[i], __shfl_xor_sync(0xffffffffu, rmin[i], o));
    }
    if (tx == 0) {
        #pragma unroll
        for (int i = 0; i < MICRO; i++)
            atomicMax(&g_key[b * NPTS + r0 + i], ~__float_as_uint(rmin[i]));
    }

    // --- last-block reduction (no second launch) ---
    __threadfence();                       // order this thread's REDGs
    __syncthreads();
    if (threadIdx.x == 0)
        s_ticket = atomicAdd(&g_cnt, 1u);  // release/acquire point
    __syncthreads();
    if (s_ticket != GRID_T - 1) return;

    // All blocks' fenced REDGs visible. Read via L2 (__ldcg), restore zeros.
    float sum = 0.0f;
    uint4* base = reinterpret_cast<uint4*>(g_key);
    #pragma unroll 4
    for (int i = threadIdx.x; i < NKEY / 4; i += THREADS) {
        const uint4 k = __ldcg(base + i);
        base[i] = make_uint4(0u, 0u, 0u, 0u);
        sum += __uint_as_float(~k.x) + __uint_as_float(~k.y)
             + __uint_as_float(~k.z) + __uint_as_float(~k.w);
    }
    #pragma unroll
    for (int o = 16; o; o >>= 1)
        sum += __shfl_xor_sync(0xffffffffu, sum, o);
    if (lane == 0) s_sum[warp] = sum;
    __syncthreads();
    if (threadIdx.x == 0) {
        float v = 0.0f;
        #pragma unroll
        for (int w = 0; w < 8; w++) v += s_sum[w];
        out[0] = v * (1.0f / ((float)BATCH * (float)NPTS));
        g_cnt = 0u;                        // reset for next replay
    }
}

extern "C" void kernel_launch(void* const* d_in, const int* in_sizes, int n_in,
                              void* d_out, int out_size) {
    const float* pred = (const float*)d_in[0];
    const float* gt   = (const float*)d_in[1];
    float* out = (float*)d_out;
    (void)in_sizes; (void)n_in; (void)out_size;

    dim3 grid(CGRPS, NBLK, BATCH);    // 8 x 32 x 4 = 1024 blocks
    chamfer_onekernel<<<grid, THREADS>>>(pred, gt, out);
}

// round 9
// speedup vs baseline: 1.0703x; 1.0011x over previous
#include <cuda_runtime.h>

#define BATCH   4
#define NPTS    4096
#define TS      128
#define MICRO   8
#define TDIM    16
#define THREADS (TDIM * TDIM)        // 256
#define NBLK    (NPTS / TS)          // 32 tiles per dim
#define CTPB    4                    // col tiles per block
#define CGRPS   (NBLK / CTPB)        // 8
#define GRID_T  (CGRPS * NBLK * BATCH)   // 1024 blocks
#define HALFK   (BATCH * NPTS)       // 16384
#define NKEY    (2 * HALFK)          // 32768 keys = 128 KB

// Bit-inverted distance keys: key = ~bits(d), d>=0 => max(key) == min(d) and
// every valid key > 0, so ZERO is the identity. The last-ticket block restores
// zeros after consuming, so every graph replay starts clean. No init kernel.
__device__ unsigned g_key[NKEY];
__device__ unsigned g_cnt;           // zero-init; reset by last block

__device__ __forceinline__ float fsub1(float a, float b) {   // a - b, FFMA-imm
    float r;
    asm("fma.rn.f32 %0, %1, 0fBF800000, %2;" : "=f"(r) : "f"(b), "f"(a));
    return r;
}

// Load 8 xyz points (24 contiguous floats, 16B-aligned) into named registers.
// Explicit component wiring — NO pointer into a local array, so ptxas keeps
// everything in registers (no STL/LDL).
__device__ __forceinline__ void load8pts(const float* __restrict__ p, int idx,
                                         float* x, float* y, float* z) {
    const float4* q = reinterpret_cast<const float4*>(p + idx * 3);
    const float4 a0 = q[0], a1 = q[1], a2 = q[2],
                 a3 = q[3], a4 = q[4], a5 = q[5];
    x[0] = a0.x; y[0] = a0.y; z[0] = a0.z;
    x[1] = a0.w; y[1] = a1.x; z[1] = a1.y;
    x[2] = a1.z; y[2] = a1.w; z[2] = a2.x;
    x[3] = a2.y; y[3] = a2.z; z[3] = a2.w;
    x[4] = a3.x; y[4] = a3.y; z[4] = a3.z;
    x[5] = a3.w; y[5] = a4.x; z[5] = a4.y;
    x[6] = a4.z; y[6] = a4.w; z[6] = a5.x;
    x[7] = a5.y; y[7] = a5.z; z[7] = a5.w;
}

__global__ __launch_bounds__(THREADS, 3)
void chamfer_onekernel(const float* __restrict__ pred,
                       const float* __restrict__ gt,
                       float* __restrict__ out) {
    const int tx   = threadIdx.x & (TDIM - 1);
    const int ty   = threadIdx.x >> 4;
    const int cgrp = blockIdx.x;          // 0..7  (4 col tiles each)
    const int rblk = blockIdx.y;          // 0..31
    const int b    = blockIdx.z;

    __shared__ float    swcol[2][8][TS];  // double-buffered: 1 sync per tile
    __shared__ unsigned s_ticket;
    __shared__ float    s_sum[8];

    const float* prow = pred + (size_t)b * NPTS * 3;
    const float* pcol = gt   + (size_t)b * NPTS * 3;
    const int r0 = rblk * TS + ty * MICRO;

    float rx[MICRO], ry[MICRO], rz[MICRO], rmin[MICRO];
    load8pts(prow, r0, rx, ry, rz);
    #pragma unroll
    for (int i = 0; i < MICRO; i++) rmin[i] = 3.4e38f;

    const int warp = threadIdx.x >> 5;
    const int lane = threadIdx.x & 31;

    #pragma unroll 1
    for (int t = 0; t < CTPB; t++) {
        const int cbase = (cgrp * CTPB + t) * TS;
        const int buf = t & 1;

        float cx[MICRO], cy[MICRO], cz[MICRO], cmin[MICRO];
        load8pts(pcol, cbase + tx * MICRO, cx, cy, cz);
        #pragma unroll
        for (int j = 0; j < MICRO; j++) cmin[j] = 3.4e38f;

        // 64 pairs: 3 FFMA-imm + 2 FADD (|.| folded) + 2 FMNMX
        #pragma unroll
        for (int i = 0; i < MICRO; i++) {
            #pragma unroll
            for (int j = 0; j < MICRO; j++) {
                const float dx = fsub1(rx[i], cx[j]);
                const float dy = fsub1(ry[i], cy[j]);
                const float dz = fsub1(rz[i], cz[j]);
                const float d  = (fabsf(dx) + fabsf(dy)) + fabsf(dz);
                rmin[i] = fminf(rmin[i], d);
                cmin[j] = fminf(cmin[j], d);
            }
        }

        // Col epilogue: xor16 fold, lanes<16 STS, min across 8 warps, REDG.MAX
        #pragma unroll
        for (int j = 0; j < MICRO; j++)
            cmin[j] = fminf(cmin[j], __shfl_xor_sync(0xffffffffu, cmin[j], 16));
        if (lane < 16) {
            #pragma unroll
            for (int j = 0; j < MICRO; j++)
                swcol[buf][warp][lane * MICRO + j] = cmin[j];
        }
        __syncthreads();
        if (threadIdx.x < TS) {
            float m = swcol[buf][0][threadIdx.x];
            #pragma unroll
            for (int w = 1; w < 8; w++)
                m = fminf(m, swcol[buf][w][threadIdx.x]);
            atomicMax(&g_key[HALFK + b * NPTS + cbase + threadIdx.x],
                      ~__float_as_uint(m));
        }
        // no second sync: next tile writes the other buffer
    }

    // Row epilogue (once): fold across the 16 tx lanes, tx==0 publishes.
    #pragma unroll
    for (int i = 0; i < MICRO; i++) {
        #pragma unroll
        for (int o = 1; o < TDIM; o <<= 1)
            rmin[i] = fminf(rmin[i], __shfl_xor_sync(0xffffffffu, rmin[i], o));
    }
    if (tx == 0) {
        #pragma unroll
        for (int i = 0; i < MICRO; i++)
            atomicMax(&g_key[b * NPTS + r0 + i], ~__float_as_uint(rmin[i]));
    }

    // --- last-block reduction (no second launch) ---
    __threadfence();                       // order this thread's REDGs
    __syncthreads();
    if (threadIdx.x == 0)
        s_ticket = atomicAdd(&g_cnt, 1u);  // release/acquire point
    __syncthreads();
    if (s_ticket != GRID_T - 1) return;

    // All blocks' fenced REDGs visible. Read via L2 (__ldcg), restore zeros.
    float sum = 0.0f;
    uint4* base = reinterpret_cast<uint4*>(g_key);
    #pragma unroll 4
    for (int i = threadIdx.x; i < NKEY / 4; i += THREADS) {
        const uint4 k = __ldcg(base + i);
        base[i] = make_uint4(0u, 0u, 0u, 0u);
        sum += __uint_as_float(~k.x) + __uint_as_float(~k.y)
             + __uint_as_float(~k.z) + __uint_as_float(~k.w);
    }
    #pragma unroll
    for (int o = 16; o; o >>= 1)
        sum += __shfl_xor_sync(0xffffffffu, sum, o);
    if (lane == 0) s_sum[warp] = sum;
    __syncthreads();
    if (threadIdx.x == 0) {
        float v = 0.0f;
        #pragma unroll
        for (int w = 0; w < 8; w++) v += s_sum[w];
        out[0] = v * (1.0f / ((float)BATCH * (float)NPTS));
        g_cnt = 0u;                        // reset for next replay
    }
}

extern "C" void kernel_launch(void* const* d_in, const int* in_sizes, int n_in,
                              void* d_out, int out_size) {
    const float* pred = (const float*)d_in[0];
    const float* gt   = (const float*)d_in[1];
    float* out = (float*)d_out;
    (void)in_sizes; (void)n_in; (void)out_size;

    dim3 grid(CGRPS, NBLK, BATCH);    // 8 x 32 x 4 = 1024 blocks
    chamfer_onekernel<<<grid, THREADS>>>(pred, gt, out);
}

// round 10
// speedup vs baseline: 1.1390x; 1.0643x over previous
#include <cuda_runtime.h>

#define BATCH   4
#define NPTS    4096
#define TS      128
#define MICRO   8
#define TDIM    16
#define THREADS 256
#define NBLK    (NPTS / TS)          // 32
#define CTPB    4                    // col tiles per block (staged together)
#define CGRPS   (NBLK / CTPB)        // 8
#define GRID_T  (CGRPS * NBLK * BATCH)   // 1024
#define HALFK   (BATCH * NPTS)       // 16384
#define NKEY    (2 * HALFK)          // 32768 keys = 128 KB

// key = ~bits(d), d>=0: max(key)==min(d), zero is identity (no init kernel;
// reduce_kernel restores zeros + resets g_acc/g_cnt each launch).
__device__ unsigned g_key[NKEY];
__device__ float    g_acc;
__device__ unsigned g_cnt;

__device__ __forceinline__ float fsub1(float a, float b) {   // a-b, FFMA-imm
    float r;
    asm("fma.rn.f32 %0, %1, 0fBF800000, %2;" : "=f"(r) : "f"(b), "f"(a));
    return r;
}

// (u,v) = rst - cst as one packed fma.rn.f32x2 (FFMA2)
__device__ __forceinline__ void psub(unsigned long long cst,
                                     unsigned long long rst,
                                     unsigned long long neg1,
                                     float& u, float& v) {
    asm("{\n\t.reg .b64 t;\n\t"
        "fma.rn.f32x2 t, %2, %3, %4;\n\t"
        "mov.b64 {%0,%1}, t;\n\t}"
        : "=f"(u), "=f"(v) : "l"(cst), "l"(neg1), "l"(rst));
}

// 8 xyz points (24 contiguous floats, 16B aligned) -> named registers
__device__ __forceinline__ void load8pts(const float* __restrict__ p, int idx,
                                         float* x, float* y, float* z) {
    const float4* q = reinterpret_cast<const float4*>(p + idx * 3);
    const float4 a0 = q[0], a1 = q[1], a2 = q[2],
                 a3 = q[3], a4 = q[4], a5 = q[5];
    x[0] = a0.x; y[0] = a0.y; z[0] = a0.z;
    x[1] = a0.w; y[1] = a1.x; z[1] = a1.y;
    x[2] = a1.z; y[2] = a1.w; z[2] = a2.x;
    x[3] = a2.y; y[3] = a2.z; z[3] = a2.w;
    x[4] = a3.x; y[4] = a3.y; z[4] = a3.z;
    x[5] = a3.w; y[5] = a4.x; z[5] = a4.y;
    x[6] = a4.z; y[6] = a4.w; z[6] = a5.x;
    x[7] = a5.y; y[7] = a5.z; z[7] = a5.w;
}

__global__ __launch_bounds__(THREADS, 3)
void chamfer_main(const float* __restrict__ pred,
                  const float* __restrict__ gt) {
    const int tx   = threadIdx.x & (TDIM - 1);
    const int ty   = threadIdx.x >> 4;
    const int cgrp = blockIdx.x;          // 0..7
    const int rblk = blockIdx.y;          // 0..31
    const int b    = blockIdx.z;

    // Padded stage (idx = p + p/8): a thread's 8 points sit at stride 9
    // elements -> 16 tx-lanes hit 16 distinct banks (1 wavefront per LDS).
    __shared__ float2 sst[576];           // (s,t) = (x+y, x-y) per col point
    __shared__ float  szs[576];           // z per col point
    __shared__ float  swcol[2][8][TS];    // double-buffered col partials

    if (cgrp == 0 && rblk == 0 && b == 0 && threadIdx.x == 0) {
        g_acc = 0.0f; g_cnt = 0u;         // redundant w/ reduce restore; cheap
    }

    const float* prow = pred + (size_t)b * NPTS * 3;
    const float* pcol = gt   + (size_t)b * NPTS * 3;

    // Stage all 4 col tiles (512 points) once, coalesced.
    const int pbase = cgrp * 512;
    #pragma unroll
    for (int k = 0; k < 2; k++) {
        const int p = threadIdx.x + k * 256;
        const float x = pcol[(pbase + p) * 3 + 0];
        const float y = pcol[(pbase + p) * 3 + 1];
        const float z = pcol[(pbase + p) * 3 + 2];
        const int s = p + (p >> 3);
        sst[s] = make_float2(x + y, x - y);
        szs[s] = z;
    }

    // Row points -> (s,t) packed pairs + z
    const int r0 = rblk * TS + ty * MICRO;
    float rx[MICRO], ry[MICRO], rz[MICRO], rmin[MICRO];
    load8pts(prow, r0, rx, ry, rz);
    unsigned long long rst[MICRO];
    #pragma unroll
    for (int i = 0; i < MICRO; i++) {
        const float s = rx[i] + ry[i], t = rx[i] - ry[i];
        asm("mov.b64 %0, {%1,%2};" : "=l"(rst[i]) : "f"(s), "f"(t));
        rmin[i] = 3.4e38f;
    }
    const unsigned long long NEG1 = 0xBF800000BF800000ULL;
    const int warp = threadIdx.x >> 5;
    const int lane = threadIdx.x & 31;
    __syncthreads();                      // stage ready

    #pragma unroll 1
    for (int t = 0; t < CTPB; t++) {
        const int cbase = (cgrp * CTPB + t) * TS;
        const int sbase = t * 144 + tx * 9;     // padded stage index
        const int buf = t & 1;

        unsigned long long cst[MICRO];
        float cz[MICRO], cmin[MICRO];
        #pragma unroll
        for (int j = 0; j < MICRO; j++) {
            cst[j] = *reinterpret_cast<const unsigned long long*>(&sst[sbase + j]);
            cz[j]  = szs[sbase + j];
            cmin[j] = 3.4e38f;
        }

        // 64 pairs x 6 inst: FFMA2 + FFMA-imm + FMNMX(|u|,|v|) + FADD(|dz|)
        // + 2 FMNMX.  (|dx|+|dy| = max(|dx+dy|,|dx-dy|))
        #pragma unroll
        for (int i = 0; i < MICRO; i++) {
            #pragma unroll
            for (int j = 0; j < MICRO; j++) {
                float u, v;
                psub(cst[j], rst[i], NEG1, u, v);
                const float dz = fsub1(rz[i], cz[j]);
                const float d  = fmaxf(fabsf(u), fabsf(v)) + fabsf(dz);
                rmin[i] = fminf(rmin[i], d);
                cmin[j] = fminf(cmin[j], d);
            }
        }

        // Col epilogue: xor16 fold, lanes<16 STS, cross-warp min, REDG.MAX
        #pragma unroll
        for (int j = 0; j < MICRO; j++)
            cmin[j] = fminf(cmin[j], __shfl_xor_sync(0xffffffffu, cmin[j], 16));
        if (lane < 16) {
            #pragma unroll
            for (int j = 0; j < MICRO; j++)
                swcol[buf][warp][lane * MICRO + j] = cmin[j];
        }
        __syncthreads();
        if (threadIdx.x < TS) {
            float m = swcol[buf][0][threadIdx.x];
            #pragma unroll
            for (int w = 1; w < 8; w++)
                m = fminf(m, swcol[buf][w][threadIdx.x]);
            atomicMax(&g_key[HALFK + b * NPTS + cbase + threadIdx.x],
                      ~__float_as_uint(m));
        }
        // next tile writes the other swcol buffer; stage is read-only
    }

    // Row epilogue: fold across the 16 tx lanes, tx==0 publishes.
    #pragma unroll
    for (int i = 0; i < MICRO; i++) {
        #pragma unroll
        for (int o = 1; o < TDIM; o <<= 1)
            rmin[i] = fminf(rmin[i], __shfl_xor_sync(0xffffffffu, rmin[i], o));
    }
    if (tx == 0) {
        #pragma unroll
        for (int i = 0; i < MICRO; i++)
            atomicMax(&g_key[b * NPTS + r0 + i], ~__float_as_uint(rmin[i]));
    }
}

// 32 blocks x 256 threads: 1 uint4 per thread, restore zeros, sum, ticket out.
__global__ __launch_bounds__(256)
void reduce_kernel(float* __restrict__ out) {
    __shared__ float sw[8];
    const int t = blockIdx.x * 256 + threadIdx.x;     // 0..8191

    uint4* p = reinterpret_cast<uint4*>(g_key) + t;
    const uint4 k = *p;
    *p = make_uint4(0u, 0u, 0u, 0u);                  // restore identity

    float sum = __uint_as_float(~k.x) + __uint_as_float(~k.y)
              + __uint_as_float(~k.z) + __uint_as_float(~k.w);

    #pragma unroll
    for (int o = 16; o; o >>= 1)
        sum += __shfl_xor_sync(0xffffffffu, sum, o);
    if ((threadIdx.x & 31) == 0) sw[threadIdx.x >> 5] = sum;
    __syncthreads();

    if (threadIdx.x == 0) {
        float v = 0.0f;
        #pragma unroll
        for (int w = 0; w < 8; w++) v += sw[w];
        atomicAdd(&g_acc, v);
        __threadfence();
        const unsigned ticket = atomicAdd(&g_cnt, 1u);
        if (ticket == 31u) {
            const float total = atomicAdd(&g_acc, 0.0f);  // coherent read
            out[0] = total * (1.0f / ((float)BATCH * (float)NPTS));
            __threadfence();
            g_acc = 0.0f;
            g_cnt = 0u;
        }
    }
}

extern "C" void kernel_launch(void* const* d_in, const int* in_sizes, int n_in,
                              void* d_out, int out_size) {
    const float* pred = (const float*)d_in[0];
    const float* gt   = (const float*)d_in[1];
    float* out = (float*)d_out;
    (void)in_sizes; (void)n_in; (void)out_size;

    dim3 grid(CGRPS, NBLK, BATCH);    // 8 x 32 x 4 = 1024 blocks
    chamfer_main<<<grid, THREADS>>>(pred, gt);
    reduce_kernel<<<NKEY / 4 / 256, 256>>>(out);
}